// round 5
// baseline (speedup 1.0000x reference)
#include <cuda_runtime.h>

#define N 256
#define BIG 1e9f

// Monotone float -> uint mapping (order-preserving), and exact inverse.
__device__ __forceinline__ unsigned fkey(float f) {
    unsigned b = __float_as_uint(f);
    return ((int)b < 0) ? ~b : (b | 0x80000000u);
}
__device__ __forceinline__ float unfkey(unsigned k) {
    unsigned b = ((int)k < 0) ? (k & 0x7FFFFFFFu) : ~k;
    return __uint_as_float(b);
}

// Jonker-Volgenant LAP, full init chain:
//   phase 1 (256 thr): column reduction  v[j] = min_i C[i][j] (+argmin row)
//   phase 2 (256 thr): greedy assignment via atomicCAS on row ownership
//   phase 2b (warp):   augmenting row reduction, 2 passes (JV lap.cpp style):
//                      per free row: warp min+2nd-min scan, tighten v[jmin],
//                      assign, kick previous holder for immediate reprocess.
//                      Iteration-capped; leftovers go to augmentation, so
//                      exactness never depends on ARR convergence.
//   phase 3 (warp):    absolute-distance Dijkstra augmentation (validated
//                      R2-R4). ARR's nonzero u0 for a free row is a pure
//                      Dijkstra source shift: cancels in all v/u updates.
// Optimum for continuous random costs is unique => matches reference.
__global__ __launch_bounds__(256, 1)
void lap_jv5(const float* __restrict__ C, float* __restrict__ out) {
    __shared__ float u0[N + 1];
    __shared__ float vinit[N + 1];
    __shared__ int   p[N + 1];      // col -> row (0 = free)
    __shared__ int   way[N + 1];
    __shared__ int   rmin[N + 1];   // col -> argmin row (phase 1)
    __shared__ int   xrow[N + 1];   // row ownership / scratch
    __shared__ int   freelist[N];
    __shared__ int   sh_nfree;

    const int tid = threadIdx.x;

    // ---- phase 1: column reduction (coalesced)
    {
        float best = C[tid];
        int   bi   = 0;
        #pragma unroll 8
        for (int i = 1; i < N; ++i) {
            const float c = C[i * N + tid];
            if (c < best) { best = c; bi = i; }
        }
        vinit[tid + 1] = best;
        rmin[tid + 1]  = bi + 1;
        u0[tid + 1]    = 0.0f;
        p[tid + 1]     = 0;
        xrow[tid + 1]  = 0;
        if (tid == 0) { u0[0] = 0.0f; vinit[0] = 0.0f; p[0] = 0; xrow[0] = 0; }
    }
    __syncthreads();

    // ---- phase 2: parallel greedy (any maximal greedy is fine; unique optimum)
    {
        const int j = tid + 1;
        const int r = rmin[j];
        if (atomicCAS(&xrow[r], 0, j) == 0) p[j] = r;
    }
    __syncthreads();
    if (tid == 0) {
        int nf = 0;
        for (int r = 1; r <= N; ++r) if (xrow[r] == 0) freelist[nf++] = r;
        sh_nfree = nf;
    }
    __syncthreads();

    if (tid < 32) {
        const int lane = tid;
        float v[8], dist[8];
        #pragma unroll
        for (int k = 0; k < 8; ++k) v[k] = vinit[lane + 1 + 32 * k];

        // ---- phase 2b: augmenting row reduction, 2 passes, iteration-capped
        {
            int numfree = sh_nfree;
            int iters = 0;
            bool capped = false;
            for (int pass = 0; pass < 2 && !capped; ++pass) {
                const int prv = numfree;
                int k = 0;
                numfree = 0;
                while (k < prv) {
                    if (++iters > 6 * N) { capped = true; break; }
                    const int i = freelist[k++];

                    // warp scan of row i: min1 (argmin) + min2 of C - v
                    const float* rowp = C + (i - 1) * N + lane;
                    float d[8];
                    #pragma unroll
                    for (int s = 0; s < 8; ++s) d[s] = __ldg(rowp + 32 * s) - v[s];
                    float m1 = d[0], m2 = BIG;
                    int bk = 0;
                    #pragma unroll
                    for (int s = 1; s < 8; ++s) {
                        if (d[s] < m1)      { m2 = m1; m1 = d[s]; bk = s; }
                        else if (d[s] < m2) { m2 = d[s]; }
                    }
                    int jmin = lane + 1 + 32 * bk;
                    #pragma unroll
                    for (int off = 16; off; off >>= 1) {
                        const float om1 = __shfl_xor_sync(0xFFFFFFFFu, m1, off);
                        const int   oj  = __shfl_xor_sync(0xFFFFFFFFu, jmin, off);
                        const float om2 = __shfl_xor_sync(0xFFFFFFFFu, m2, off);
                        m2 = fminf(fminf(m2, om2), fmaxf(m1, om1));
                        if (om1 < m1) { m1 = om1; jmin = oj; }
                    }

                    const int   i0    = p[jmin];
                    const float delta = m2 - m1;
                    if (delta > 0.0f || i0 == 0) {
                        if (((jmin - 1) & 31) == lane) v[(jmin - 1) >> 5] -= delta;
                        if (lane == 0) { u0[i] = m2; p[jmin] = i; }
                        if (i0 != 0) {           // kick: immediate reprocess
                            --k;
                            if (lane == 0) freelist[k] = i0;
                        }
                    } else {                     // degenerate tie: defer row
                        if (lane == 0) freelist[numfree] = i;
                        ++numfree;
                    }
                    __syncwarp();
                }
            }
        }

        // rebuild free-row list from p (robust to ARR cap/degenerate exits)
        for (int r = lane + 1; r <= N; r += 32) xrow[r] = 0;
        __syncwarp();
        for (int j = lane + 1; j <= N; j += 32) {
            const int r = p[j];
            if (r) xrow[r] = 1;                  // distinct rows: no conflict
        }
        __syncwarp();
        if (lane == 0) {
            int nf = 0;
            for (int r = 1; r <= N; ++r) if (!xrow[r]) freelist[nf++] = r;
            sh_nfree = nf;
        }
        __syncwarp();

        // ---- phase 3: Dijkstra augmentation per remaining free row
        const int nf = sh_nfree;
        for (int fr = 0; fr < nf; ++fr) {
            const int i = freelist[fr];
            #pragma unroll
            for (int k = 0; k < 8; ++k) dist[k] = BIG;
            unsigned usedmask = 0;
            float Dsum = 0.0f;
            int j0 = 0, i0 = i, jfree;
            if (lane == 0) p[0] = i;

            for (;;) {
                const float* rowp = C + (i0 - 1) * N + lane;
                float cc[8];
                #pragma unroll
                for (int k = 0; k < 8; ++k) cc[k] = __ldg(rowp + 32 * k);
                const float ui = u0[i0];
                {
                    const int jz = j0 - 1;
                    if ((jz & 31) == lane && jz >= 0) usedmask |= 1u << (jz >> 5);
                }

                #pragma unroll
                for (int k = 0; k < 8; ++k) {
                    const float cur = cc[k] - ui - v[k] + Dsum;
                    if (!((usedmask >> k) & 1u) && cur < dist[k]) {
                        dist[k] = cur;
                        way[lane + 1 + 32 * k] = j0;
                    }
                }

                float av[8];
                #pragma unroll
                for (int k = 0; k < 8; ++k)
                    av[k] = ((usedmask >> k) & 1u) ? __int_as_float(0x7F800000)
                                                   : dist[k];
                const float m0 = fminf(av[0], av[1]), m1 = fminf(av[2], av[3]);
                const float m2 = fminf(av[4], av[5]), m3 = fminf(av[6], av[7]);
                const float bv = fminf(fminf(m0, m1), fminf(m2, m3));

                const unsigned key  = fkey(bv);
                const unsigned kmin = __reduce_min_sync(0xFFFFFFFFu, key);

                int bk = 7;
                #pragma unroll
                for (int k = 6; k >= 0; --k) bk = (av[k] == bv) ? k : bk;
                const int jc = lane + 1 + 32 * bk;
                const int ic = p[jc];                 // hidden under ballot

                const unsigned ball = __ballot_sync(0xFFFFFFFFu, key == kmin);
                const int wl = __ffs(ball) - 1;
                Dsum = unfkey(kmin);
                j0 = __shfl_sync(0xFFFFFFFFu, jc, wl);
                i0 = __shfl_sync(0xFFFFFFFFu, ic, wl);
                if (i0 == 0) { jfree = j0; break; }
            }

            const float Dfinal = Dsum;
            #pragma unroll
            for (int k = 0; k < 8; ++k) {
                if ((usedmask >> k) & 1u) {
                    const float amt = Dfinal - dist[k];
                    v[k] -= amt;
                    u0[p[lane + 1 + 32 * k]] += amt;  // distinct rows: safe
                }
            }
            if (lane == 0) u0[i] += Dfinal;
            __syncwarp();

            if (lane == 0) {                          // augment path
                int jj = jfree;
                while (jj != 0) { const int j1 = way[jj]; p[jj] = p[j1]; jj = j1; }
            }
            __syncwarp();
        }
    }
    __syncthreads();

    // ---- output: 0/1 labelling
    {
        const float4 z = make_float4(0.f, 0.f, 0.f, 0.f);
        for (int idx = tid; idx < N * N / 4; idx += 256) ((float4*)out)[idx] = z;
    }
    __syncthreads();
    {
        const int col = tid;                          // 0-based column
        const int r   = p[col + 1] - 1;               // 0-based matched row
        out[r * N + col] = 1.0f;
    }
}

extern "C" void kernel_launch(void* const* d_in, const int* in_sizes, int n_in,
                              void* d_out, int out_size) {
    (void)in_sizes; (void)n_in; (void)out_size;
    lap_jv5<<<1, 256>>>((const float*)d_in[0], (float*)d_out);
}

// round 6
// speedup vs baseline: 1.2296x; 1.2296x over previous
#include <cuda_runtime.h>

#define N 256
#define BIG 1e9f

// Monotone float -> uint mapping (order-preserving), and exact inverse.
__device__ __forceinline__ unsigned fkey(float f) {
    unsigned b = __float_as_uint(f);
    return ((int)b < 0) ? ~b : (b | 0x80000000u);
}
__device__ __forceinline__ float unfkey(unsigned k) {
    unsigned b = ((int)k < 0) ? (k & 0x7FFFFFFFu) : ~k;
    return __uint_as_float(b);
}

// Jonker-Volgenant LAP:
//   phase 1 (256 thr): column reduction  v[j] = min_i C[i][j] (+argmin row)
//   phase 2 (thr 0):   greedy assignment from column argmins (as R4)
//   phase 2b (warp 0): BOUNDED augmenting row reduction: 2 passes over the
//                      free list, NO within-pass kick-reprocessing (kicked
//                      rows go to the next pass's list). Cost is exactly
//                      (|free| + |kicked|) row scans (~130), unlike R5's
//                      unbounded kick chains. Feasibility: u[i]=m2,
//                      v[jmin]-=m2-m1 keeps redcost>=0; kicked rows' stale
//                      u stays feasible since v only decreases.
//   phase 3 (warp 0):  absolute-distance Dijkstra augmentation, byte-for-
//                      byte the validated R4 loop. Phase 3's outcome is
//                      invariant to the source row's initial u0 (pure
//                      shift, cancels in all updates), so ARR composes
//                      safely.
// Optimum for continuous random costs is unique => matches reference.
__global__ __launch_bounds__(256, 1)
void lap_jv6(const float* __restrict__ C, float* __restrict__ out) {
    __shared__ float u0[N + 1];
    __shared__ float vinit[N + 1];
    __shared__ int   p[N + 1];      // col -> row (0 = free)
    __shared__ int   way[N + 1];
    __shared__ int   rmin[N + 1];   // col -> argmin row (phase 1)
    __shared__ int   xrow[N + 1];   // row ownership (phase 2)
    __shared__ int   lista[N];
    __shared__ int   listb[N];
    __shared__ int   sh_nfree;

    const int tid = threadIdx.x;

    // ---- phase 1: column reduction (coalesced)
    {
        float best = C[tid];
        int   bi   = 0;
        #pragma unroll 8
        for (int i = 1; i < N; ++i) {
            const float c = C[i * N + tid];
            if (c < best) { best = c; bi = i; }
        }
        vinit[tid + 1] = best;
        rmin[tid + 1]  = bi + 1;
        u0[tid + 1]    = 0.0f;
        p[tid + 1]     = 0;
        xrow[tid + 1]  = 0;
        if (tid == 0) { u0[0] = 0.0f; vinit[0] = 0.0f; p[0] = 0; xrow[0] = 0; }
    }
    __syncthreads();

    // ---- phase 2: greedy assignment (serial, short; as validated R4)
    if (tid == 0) {
        for (int j = 1; j <= N; ++j) {
            const int r = rmin[j];
            if (xrow[r] == 0) { xrow[r] = j; p[j] = r; }
        }
        int nf = 0;
        for (int r = 1; r <= N; ++r) if (xrow[r] == 0) lista[nf++] = r;
        sh_nfree = nf;
    }
    __syncthreads();

    if (tid < 32) {
        const int lane = tid;
        float v[8], dist[8];
        #pragma unroll
        for (int k = 0; k < 8; ++k) v[k] = vinit[lane + 1 + 32 * k];

        // ---- phase 2b: bounded ARR, 2 passes, kicked rows -> next list
        int nf_cur = sh_nfree;
        int* cur  = lista;
        int* nxt  = listb;
        #pragma unroll 1
        for (int pass = 0; pass < 2; ++pass) {
            int nf_nxt = 0;
            for (int kq = 0; kq < nf_cur; ++kq) {
                const int i = cur[kq];

                // warp scan of row i: min1 (argmin col) + min2 of C - v
                const float* rowp = C + (i - 1) * N + lane;
                float d[8];
                #pragma unroll
                for (int s = 0; s < 8; ++s) d[s] = __ldg(rowp + 32 * s) - v[s];
                float m1 = d[0], m2 = BIG;
                int bk = 0;
                #pragma unroll
                for (int s = 1; s < 8; ++s) {
                    if (d[s] < m1)      { m2 = m1; m1 = d[s]; bk = s; }
                    else if (d[s] < m2) { m2 = d[s]; }
                }
                int jmin = lane + 1 + 32 * bk;
                #pragma unroll
                for (int off = 16; off; off >>= 1) {
                    const float om1 = __shfl_xor_sync(0xFFFFFFFFu, m1, off);
                    const int   oj  = __shfl_xor_sync(0xFFFFFFFFu, jmin, off);
                    const float om2 = __shfl_xor_sync(0xFFFFFFFFu, m2, off);
                    m2 = fminf(fminf(m2, om2), fmaxf(m1, om1));
                    if (om1 < m1) { m1 = om1; jmin = oj; }
                }

                const int   i0    = p[jmin];          // uniform
                const float delta = m2 - m1;
                if (delta > 0.0f || i0 == 0) {
                    if (((jmin - 1) & 31) == lane) v[(jmin - 1) >> 5] -= delta;
                    if (lane == 0) { u0[i] = m2; p[jmin] = i; }
                    if (i0 != 0) {                    // kicked -> next pass
                        if (lane == 0) nxt[nf_nxt] = i0;
                        ++nf_nxt;                     // uniform count
                    }
                } else {                              // tie on occupied col
                    if (lane == 0) nxt[nf_nxt] = i;
                    ++nf_nxt;
                }
                __syncwarp();                         // order STS before LDS
            }
            nf_cur = nf_nxt;
            int* t = cur; cur = nxt; nxt = t;
        }

        // ---- phase 3: Dijkstra augmentation per remaining free row (R4)
        const int nf = nf_cur;
        for (int fr = 0; fr < nf; ++fr) {
            const int i = cur[fr];
            #pragma unroll
            for (int k = 0; k < 8; ++k) dist[k] = BIG;
            unsigned usedmask = 0;
            float Dsum = 0.0f;
            int j0 = 0, i0 = i, jfree;
            if (lane == 0) p[0] = i;

            for (;;) {
                const float* rowp = C + (i0 - 1) * N + lane;
                float cc[8];
                #pragma unroll
                for (int k = 0; k < 8; ++k) cc[k] = __ldg(rowp + 32 * k);
                const float ui = u0[i0];
                {
                    const int jz = j0 - 1;
                    if ((jz & 31) == lane && jz >= 0) usedmask |= 1u << (jz >> 5);
                }

                #pragma unroll
                for (int k = 0; k < 8; ++k) {
                    const float cur_d = cc[k] - ui - v[k] + Dsum;
                    if (!((usedmask >> k) & 1u) && cur_d < dist[k]) {
                        dist[k] = cur_d;
                        way[lane + 1 + 32 * k] = j0;
                    }
                }

                float av[8];
                #pragma unroll
                for (int k = 0; k < 8; ++k)
                    av[k] = ((usedmask >> k) & 1u) ? __int_as_float(0x7F800000)
                                                   : dist[k];
                const float t0 = fminf(av[0], av[1]), t1 = fminf(av[2], av[3]);
                const float t2 = fminf(av[4], av[5]), t3 = fminf(av[6], av[7]);
                const float bv = fminf(fminf(t0, t1), fminf(t2, t3));

                const unsigned key  = fkey(bv);
                const unsigned kmin = __reduce_min_sync(0xFFFFFFFFu, key);

                int bk = 7;
                #pragma unroll
                for (int k = 6; k >= 0; --k) bk = (av[k] == bv) ? k : bk;
                const int jc = lane + 1 + 32 * bk;
                const int ic = p[jc];                 // hidden under ballot

                const unsigned ball = __ballot_sync(0xFFFFFFFFu, key == kmin);
                const int wl = __ffs(ball) - 1;
                Dsum = unfkey(kmin);
                j0 = __shfl_sync(0xFFFFFFFFu, jc, wl);
                i0 = __shfl_sync(0xFFFFFFFFu, ic, wl);
                if (i0 == 0) { jfree = j0; break; }
            }

            const float Dfinal = Dsum;
            #pragma unroll
            for (int k = 0; k < 8; ++k) {
                if ((usedmask >> k) & 1u) {
                    const float amt = Dfinal - dist[k];
                    v[k] -= amt;
                    u0[p[lane + 1 + 32 * k]] += amt;  // distinct rows: safe
                }
            }
            if (lane == 0) u0[i] += Dfinal;
            __syncwarp();

            if (lane == 0) {                          // augment path
                int jj = jfree;
                while (jj != 0) { const int j1 = way[jj]; p[jj] = p[j1]; jj = j1; }
            }
            __syncwarp();
        }
    }
    __syncthreads();

    // ---- output: 0/1 labelling
    {
        const float4 z = make_float4(0.f, 0.f, 0.f, 0.f);
        for (int idx = tid; idx < N * N / 4; idx += 256) ((float4*)out)[idx] = z;
    }
    __syncthreads();
    {
        const int col = tid;                          // 0-based column
        const int r   = p[col + 1] - 1;               // 0-based matched row
        out[r * N + col] = 1.0f;
    }
}

extern "C" void kernel_launch(void* const* d_in, const int* in_sizes, int n_in,
                              void* d_out, int out_size) {
    (void)in_sizes; (void)n_in; (void)out_size;
    lap_jv6<<<1, 256>>>((const float*)d_in[0], (float*)d_out);
}

// round 7
// speedup vs baseline: 1.3958x; 1.1352x over previous
#include <cuda_runtime.h>

#define N 256
#define BIG 1e9f
#define CROWS 216   // rows of C cached in SMEM (216 KB); rest served by L2

// Monotone float -> uint mapping (order-preserving), and exact inverse.
__device__ __forceinline__ unsigned fkey(float f) {
    unsigned b = __float_as_uint(f);
    return ((int)b < 0) ? ~b : (b | 0x80000000u);
}
__device__ __forceinline__ float unfkey(unsigned k) {
    unsigned b = ((int)k < 0) ? (k & 0x7FFFFFFFu) : ~k;
    return __uint_as_float(b);
}

// Jonker-Volgenant LAP (algorithm identical to validated R6):
//   phase 1: column reduction + populate SMEM row cache (coalesced)
//   phase 2: serial greedy assignment
//   phase 2b: bounded 2-pass augmenting row reduction
//   phase 3: single-warp absolute-distance Dijkstra augmentation
// New in R7: rows 1..CROWS of C are served from a dynamic-SMEM cache
// (bit-identical fp32), turning ~84% of critical-chain row loads from
// exposed L2 hits (~250 cyc) into conflict-free LDS (~29 cyc).
__global__ __launch_bounds__(256, 1)
void lap_jv7(const float* __restrict__ C, float* __restrict__ out) {
    extern __shared__ float smem_dyn[];
    float* Ccache = smem_dyn;                      // [CROWS][256]
    float* u0     = Ccache + CROWS * 256;          // [N+1]
    float* vinit  = u0 + (N + 1);                  // [N+1]
    int*   p      = (int*)(vinit + (N + 1));       // [N+1] col -> row (0=free)
    int*   way    = p + (N + 1);                   // [N+1]
    int*   rmin   = way + (N + 1);                 // [N+1]
    int*   xrow   = rmin + (N + 1);                // [N+1]
    int*   lista  = xrow + (N + 1);                // [N]
    int*   listb  = lista + N;                     // [N]
    int*   sh_nfree = listb + N;                   // [1]

    const int tid = threadIdx.x;

    // ---- phase 1: column reduction + fill SMEM row cache (coalesced)
    {
        float best = C[tid];
        int   bi   = 0;
        Ccache[tid] = best;                        // row 0
        #pragma unroll 8
        for (int i = 1; i < N; ++i) {
            const float c = C[i * N + tid];
            if (i < CROWS) Ccache[i * 256 + tid] = c;
            if (c < best) { best = c; bi = i; }
        }
        vinit[tid + 1] = best;
        rmin[tid + 1]  = bi + 1;
        u0[tid + 1]    = 0.0f;
        p[tid + 1]     = 0;
        xrow[tid + 1]  = 0;
        if (tid == 0) { u0[0] = 0.0f; vinit[0] = 0.0f; p[0] = 0; xrow[0] = 0; }
    }
    __syncthreads();

    // ---- phase 2: greedy assignment (serial, short)
    if (tid == 0) {
        for (int j = 1; j <= N; ++j) {
            const int r = rmin[j];
            if (xrow[r] == 0) { xrow[r] = j; p[j] = r; }
        }
        int nf = 0;
        for (int r = 1; r <= N; ++r) if (xrow[r] == 0) lista[nf++] = r;
        *sh_nfree = nf;
    }
    __syncthreads();

    if (tid < 32) {
        const int lane = tid;
        float v[8], dist[8];
        #pragma unroll
        for (int k = 0; k < 8; ++k) v[k] = vinit[lane + 1 + 32 * k];

        // ---- phase 2b: bounded ARR, 2 passes, kicked rows -> next list
        int nf_cur = *sh_nfree;
        int* cur  = lista;
        int* nxt  = listb;
        #pragma unroll 1
        for (int pass = 0; pass < 2; ++pass) {
            int nf_nxt = 0;
            for (int kq = 0; kq < nf_cur; ++kq) {
                const int i = cur[kq];

                // warp scan of row i: min1 (argmin col) + min2 of C - v
                float d[8];
                if (i <= CROWS) {
                    const float* rs = Ccache + (i - 1) * 256 + lane;
                    #pragma unroll
                    for (int s = 0; s < 8; ++s) d[s] = rs[32 * s] - v[s];
                } else {
                    const float* rowp = C + (i - 1) * N + lane;
                    #pragma unroll
                    for (int s = 0; s < 8; ++s) d[s] = __ldg(rowp + 32 * s) - v[s];
                }
                float m1 = d[0], m2 = BIG;
                int bk = 0;
                #pragma unroll
                for (int s = 1; s < 8; ++s) {
                    if (d[s] < m1)      { m2 = m1; m1 = d[s]; bk = s; }
                    else if (d[s] < m2) { m2 = d[s]; }
                }
                int jmin = lane + 1 + 32 * bk;
                #pragma unroll
                for (int off = 16; off; off >>= 1) {
                    const float om1 = __shfl_xor_sync(0xFFFFFFFFu, m1, off);
                    const int   oj  = __shfl_xor_sync(0xFFFFFFFFu, jmin, off);
                    const float om2 = __shfl_xor_sync(0xFFFFFFFFu, m2, off);
                    m2 = fminf(fminf(m2, om2), fmaxf(m1, om1));
                    if (om1 < m1) { m1 = om1; jmin = oj; }
                }

                const int   i0    = p[jmin];          // uniform
                const float delta = m2 - m1;
                if (delta > 0.0f || i0 == 0) {
                    if (((jmin - 1) & 31) == lane) v[(jmin - 1) >> 5] -= delta;
                    if (lane == 0) { u0[i] = m2; p[jmin] = i; }
                    if (i0 != 0) {                    // kicked -> next pass
                        if (lane == 0) nxt[nf_nxt] = i0;
                        ++nf_nxt;
                    }
                } else {                              // tie on occupied col
                    if (lane == 0) nxt[nf_nxt] = i;
                    ++nf_nxt;
                }
                __syncwarp();
            }
            nf_cur = nf_nxt;
            int* t = cur; cur = nxt; nxt = t;
        }

        // ---- phase 3: Dijkstra augmentation per remaining free row
        const int nf = nf_cur;
        for (int fr = 0; fr < nf; ++fr) {
            const int i = cur[fr];
            #pragma unroll
            for (int k = 0; k < 8; ++k) dist[k] = BIG;
            unsigned usedmask = 0;
            float Dsum = 0.0f;
            int j0 = 0, i0 = i, jfree;
            if (lane == 0) p[0] = i;

            for (;;) {
                float cc[8];
                if (i0 <= CROWS) {
                    const float* rs = Ccache + (i0 - 1) * 256 + lane;
                    #pragma unroll
                    for (int k = 0; k < 8; ++k) cc[k] = rs[32 * k];
                } else {
                    const float* rowp = C + (i0 - 1) * N + lane;
                    #pragma unroll
                    for (int k = 0; k < 8; ++k) cc[k] = __ldg(rowp + 32 * k);
                }
                const float ui = u0[i0];
                {
                    const int jz = j0 - 1;
                    if ((jz & 31) == lane && jz >= 0) usedmask |= 1u << (jz >> 5);
                }

                #pragma unroll
                for (int k = 0; k < 8; ++k) {
                    const float cur_d = cc[k] - ui - v[k] + Dsum;
                    if (!((usedmask >> k) & 1u) && cur_d < dist[k]) {
                        dist[k] = cur_d;
                        way[lane + 1 + 32 * k] = j0;
                    }
                }

                float av[8];
                #pragma unroll
                for (int k = 0; k < 8; ++k)
                    av[k] = ((usedmask >> k) & 1u) ? __int_as_float(0x7F800000)
                                                   : dist[k];
                const float t0 = fminf(av[0], av[1]), t1 = fminf(av[2], av[3]);
                const float t2 = fminf(av[4], av[5]), t3 = fminf(av[6], av[7]);
                const float bv = fminf(fminf(t0, t1), fminf(t2, t3));

                const unsigned key  = fkey(bv);
                const unsigned kmin = __reduce_min_sync(0xFFFFFFFFu, key);

                int bk = 7;
                #pragma unroll
                for (int k = 6; k >= 0; --k) bk = (av[k] == bv) ? k : bk;
                const int jc = lane + 1 + 32 * bk;
                const int ic = p[jc];                 // hidden under ballot

                const unsigned ball = __ballot_sync(0xFFFFFFFFu, key == kmin);
                const int wl = __ffs(ball) - 1;
                Dsum = unfkey(kmin);
                j0 = __shfl_sync(0xFFFFFFFFu, jc, wl);
                i0 = __shfl_sync(0xFFFFFFFFu, ic, wl);
                if (i0 == 0) { jfree = j0; break; }
            }

            const float Dfinal = Dsum;
            #pragma unroll
            for (int k = 0; k < 8; ++k) {
                if ((usedmask >> k) & 1u) {
                    const float amt = Dfinal - dist[k];
                    v[k] -= amt;
                    u0[p[lane + 1 + 32 * k]] += amt;  // distinct rows: safe
                }
            }
            if (lane == 0) u0[i] += Dfinal;
            __syncwarp();

            if (lane == 0) {                          // augment path
                int jj = jfree;
                while (jj != 0) { const int j1 = way[jj]; p[jj] = p[j1]; jj = j1; }
            }
            __syncwarp();
        }
    }
    __syncthreads();

    // ---- output: 0/1 labelling
    {
        const float4 z = make_float4(0.f, 0.f, 0.f, 0.f);
        for (int idx = tid; idx < N * N / 4; idx += 256) ((float4*)out)[idx] = z;
    }
    __syncthreads();
    {
        const int col = tid;                          // 0-based column
        const int r   = p[col + 1] - 1;               // 0-based matched row
        out[r * N + col] = 1.0f;
    }
}

// Dynamic SMEM size: C cache + solver state
#define SMEM_BYTES (CROWS * 256 * 4 + 2 * (N + 1) * 4 + 4 * (N + 1) * 4 \
                    + 2 * N * 4 + 4)

extern "C" void kernel_launch(void* const* d_in, const int* in_sizes, int n_in,
                              void* d_out, int out_size) {
    (void)in_sizes; (void)n_in; (void)out_size;
    cudaFuncSetAttribute(lap_jv7, cudaFuncAttributeMaxDynamicSharedMemorySize,
                         SMEM_BYTES);
    lap_jv7<<<1, 256, SMEM_BYTES>>>((const float*)d_in[0], (float*)d_out);
}

// round 8
// speedup vs baseline: 1.9661x; 1.4085x over previous
#include <cuda_runtime.h>

#define N 256
#define BIG 1e9f
#define FINF __int_as_float(0x7F800000)
#define CROWS 216   // rows of C cached in SMEM; rest served by L2

// Monotone float -> uint mapping (order-preserving), and exact inverse.
__device__ __forceinline__ unsigned fkey(float f) {
    unsigned b = __float_as_uint(f);
    return ((int)b < 0) ? ~b : (b | 0x80000000u);
}
__device__ __forceinline__ float unfkey(unsigned k) {
    unsigned b = ((int)k < 0) ? (k & 0x7FFFFFFFu) : ~k;
    return __uint_as_float(b);
}

// Column ownership (0-based): lane owns col(k) = 64*(k>>1) + 2*lane + (k&1),
// k = 0..7 (4 adjacent pairs -> float2 loads, conflict-free LDS.64).
// Inverse: lane = (c0>>1)&31, k = ((c0>>6)<<1)|(c0&1).
__device__ __forceinline__ int colof(int lane, int k) {
    return 64 * (k >> 1) + 2 * lane + (k & 1);
}

// Jonker-Volgenant LAP (same algorithm as validated R6/R7):
//   phase 1: column reduction + SMEM row cache fill
//   phase 2: serial greedy assignment
//   phase 2b: bounded 2-pass augmenting row reduction
//   phase 3: single-warp absolute-distance Dijkstra augmentation
// R8: per-step cost cuts — float2 row loads, dist-set-to-INF at mark (kills
// the min-tree masking selects; mark[] snapshots the frozen settle value,
// R2-validated semantics), and s = Dsum-ui folded once per step.
__global__ __launch_bounds__(256, 1)
void lap_jv8(const float* __restrict__ C, float* __restrict__ out) {
    extern __shared__ float smem_dyn[];
    float* Ccache = smem_dyn;                      // [CROWS][256]
    float* u0     = Ccache + CROWS * 256;          // [N+1]
    float* vinit  = u0 + (N + 1);                  // [N+1]
    int*   p      = (int*)(vinit + (N + 1));       // [N+1] col -> row (0=free)
    int*   way    = p + (N + 1);                   // [N+1]
    int*   rmin   = way + (N + 1);                 // [N+1]
    int*   xrow   = rmin + (N + 1);                // [N+1]
    int*   lista  = xrow + (N + 1);                // [N]
    int*   listb  = lista + N;                     // [N]
    int*   sh_nfree = listb + N;                   // [1]

    const int tid = threadIdx.x;

    // ---- phase 1: column reduction + fill SMEM row cache (coalesced)
    {
        float best = C[tid];
        int   bi   = 0;
        Ccache[tid] = best;                        // row 0
        #pragma unroll 8
        for (int i = 1; i < N; ++i) {
            const float c = C[i * N + tid];
            if (i < CROWS) Ccache[i * 256 + tid] = c;
            if (c < best) { best = c; bi = i; }
        }
        vinit[tid + 1] = best;
        rmin[tid + 1]  = bi + 1;
        u0[tid + 1]    = 0.0f;
        p[tid + 1]     = 0;
        xrow[tid + 1]  = 0;
        if (tid == 0) { u0[0] = 0.0f; vinit[0] = 0.0f; p[0] = 0; xrow[0] = 0; }
    }
    __syncthreads();

    // ---- phase 2: greedy assignment (serial, short)
    if (tid == 0) {
        for (int j = 1; j <= N; ++j) {
            const int r = rmin[j];
            if (xrow[r] == 0) { xrow[r] = j; p[j] = r; }
        }
        int nf = 0;
        for (int r = 1; r <= N; ++r) if (xrow[r] == 0) lista[nf++] = r;
        *sh_nfree = nf;
    }
    __syncthreads();

    if (tid < 32) {
        const int lane = tid;
        float v[8], dist[8], mark[8];
        #pragma unroll
        for (int k = 0; k < 8; ++k) v[k] = vinit[colof(lane, k) + 1];

        // ---- phase 2b: bounded ARR, 2 passes, kicked rows -> next list
        int nf_cur = *sh_nfree;
        int* cur  = lista;
        int* nxt  = listb;
        #pragma unroll 1
        for (int pass = 0; pass < 2; ++pass) {
            int nf_nxt = 0;
            for (int kq = 0; kq < nf_cur; ++kq) {
                const int i = cur[kq];

                // warp scan of row i: min1 (argmin col) + min2 of C - v
                float d[8];
                if (i <= CROWS) {
                    const float* rs = Ccache + (i - 1) * 256 + 2 * lane;
                    #pragma unroll
                    for (int s = 0; s < 4; ++s) {
                        const float2 t = *(const float2*)(rs + 64 * s);
                        d[2 * s]     = t.x - v[2 * s];
                        d[2 * s + 1] = t.y - v[2 * s + 1];
                    }
                } else {
                    const float* rowp = C + (i - 1) * N + 2 * lane;
                    #pragma unroll
                    for (int s = 0; s < 4; ++s) {
                        const float2 t = __ldg((const float2*)(rowp + 64 * s));
                        d[2 * s]     = t.x - v[2 * s];
                        d[2 * s + 1] = t.y - v[2 * s + 1];
                    }
                }
                float m1 = d[0], m2 = BIG;
                int bk = 0;
                #pragma unroll
                for (int s = 1; s < 8; ++s) {
                    if (d[s] < m1)      { m2 = m1; m1 = d[s]; bk = s; }
                    else if (d[s] < m2) { m2 = d[s]; }
                }
                int jmin = colof(lane, bk) + 1;
                #pragma unroll
                for (int off = 16; off; off >>= 1) {
                    const float om1 = __shfl_xor_sync(0xFFFFFFFFu, m1, off);
                    const int   oj  = __shfl_xor_sync(0xFFFFFFFFu, jmin, off);
                    const float om2 = __shfl_xor_sync(0xFFFFFFFFu, m2, off);
                    m2 = fminf(fminf(m2, om2), fmaxf(m1, om1));
                    if (om1 < m1) { m1 = om1; jmin = oj; }
                }

                const int   i0    = p[jmin];          // uniform
                const float delta = m2 - m1;
                if (delta > 0.0f || i0 == 0) {
                    const int c0 = jmin - 1;
                    if (((c0 >> 1) & 31) == lane)
                        v[((c0 >> 6) << 1) | (c0 & 1)] -= delta;
                    if (lane == 0) { u0[i] = m2; p[jmin] = i; }
                    if (i0 != 0) {                    // kicked -> next pass
                        if (lane == 0) nxt[nf_nxt] = i0;
                        ++nf_nxt;
                    }
                } else {                              // tie on occupied col
                    if (lane == 0) nxt[nf_nxt] = i;
                    ++nf_nxt;
                }
                __syncwarp();
            }
            nf_cur = nf_nxt;
            int* t = cur; cur = nxt; nxt = t;
        }

        // ---- phase 3: Dijkstra augmentation per remaining free row
        const int nf = nf_cur;
        for (int fr = 0; fr < nf; ++fr) {
            const int i = cur[fr];
            #pragma unroll
            for (int k = 0; k < 8; ++k) dist[k] = BIG;
            unsigned usedmask = 0;
            float Dsum = 0.0f;
            int j0 = 0, i0 = i, jfree;
            if (lane == 0) p[0] = i;

            for (;;) {
                // row loads first (v2); bookkeeping in their shadow
                float cc[8];
                if (i0 <= CROWS) {
                    const float* rs = Ccache + (i0 - 1) * 256 + 2 * lane;
                    #pragma unroll
                    for (int s = 0; s < 4; ++s) {
                        const float2 t = *(const float2*)(rs + 64 * s);
                        cc[2 * s] = t.x; cc[2 * s + 1] = t.y;
                    }
                } else {
                    const float* rowp = C + (i0 - 1) * N + 2 * lane;
                    #pragma unroll
                    for (int s = 0; s < 4; ++s) {
                        const float2 t = __ldg((const float2*)(rowp + 64 * s));
                        cc[2 * s] = t.x; cc[2 * s + 1] = t.y;
                    }
                }
                const float s0 = Dsum - u0[i0];

                // mark popped column j0: freeze value, kill from min tree
                if (j0) {
                    const int c0 = j0 - 1;
                    if (((c0 >> 1) & 31) == lane) {
                        const int k = ((c0 >> 6) << 1) | (c0 & 1);
                        usedmask |= 1u << k;
                        mark[k] = Dsum;
                        dist[k] = FINF;
                    }
                }

                #pragma unroll
                for (int k = 0; k < 8; ++k) {
                    const float cur_d = (cc[k] - v[k]) + s0;
                    if (!((usedmask >> k) & 1u) && cur_d < dist[k]) {
                        dist[k] = cur_d;
                        way[colof(lane, k) + 1] = j0;
                    }
                }

                // min tree directly on dist (used entries are +INF)
                const float t0 = fminf(dist[0], dist[1]);
                const float t1 = fminf(dist[2], dist[3]);
                const float t2 = fminf(dist[4], dist[5]);
                const float t3 = fminf(dist[6], dist[7]);
                const float bv = fminf(fminf(t0, t1), fminf(t2, t3));

                const unsigned key  = fkey(bv);
                const unsigned kmin = __reduce_min_sync(0xFFFFFFFFu, key);

                int bk = 7;
                #pragma unroll
                for (int k = 6; k >= 0; --k) bk = (dist[k] == bv) ? k : bk;
                const int jc = colof(lane, bk) + 1;
                const int ic = p[jc];                 // hidden under ballot

                const unsigned ball = __ballot_sync(0xFFFFFFFFu, key == kmin);
                const int wl = __ffs(ball) - 1;
                Dsum = unfkey(kmin);
                j0 = __shfl_sync(0xFFFFFFFFu, jc, wl);
                i0 = __shfl_sync(0xFFFFFFFFu, ic, wl);
                if (i0 == 0) { jfree = j0; break; }
            }

            // end-of-row dual updates from mark[] (settle-time Dsum values)
            const float Dfinal = Dsum;
            #pragma unroll
            for (int k = 0; k < 8; ++k) {
                if ((usedmask >> k) & 1u) {
                    const float amt = Dfinal - mark[k];
                    v[k] -= amt;
                    u0[p[colof(lane, k) + 1]] += amt; // distinct rows: safe
                }
            }
            if (lane == 0) u0[i] += Dfinal;
            __syncwarp();

            if (lane == 0) {                          // augment path
                int jj = jfree;
                while (jj != 0) { const int j1 = way[jj]; p[jj] = p[j1]; jj = j1; }
            }
            __syncwarp();
        }
    }
    __syncthreads();

    // ---- output: 0/1 labelling
    {
        const float4 z = make_float4(0.f, 0.f, 0.f, 0.f);
        for (int idx = tid; idx < N * N / 4; idx += 256) ((float4*)out)[idx] = z;
    }
    __syncthreads();
    {
        const int col = tid;                          // 0-based column
        const int r   = p[col + 1] - 1;               // 0-based matched row
        out[r * N + col] = 1.0f;
    }
}

// Dynamic SMEM size: C cache + solver state
#define SMEM_BYTES (CROWS * 256 * 4 + 2 * (N + 1) * 4 + 4 * (N + 1) * 4 \
                    + 2 * N * 4 + 4)

extern "C" void kernel_launch(void* const* d_in, const int* in_sizes, int n_in,
                              void* d_out, int out_size) {
    (void)in_sizes; (void)n_in; (void)out_size;
    cudaFuncSetAttribute(lap_jv8, cudaFuncAttributeMaxDynamicSharedMemorySize,
                         SMEM_BYTES);
    lap_jv8<<<1, 256, SMEM_BYTES>>>((const float*)d_in[0], (float*)d_out);
}

// round 9
// speedup vs baseline: 2.0242x; 1.0296x over previous
#include <cuda_runtime.h>

#define N 256
#define BIG 1e9f
#define FINF __int_as_float(0x7F800000)
#define CROWS 216   // rows of C cached in SMEM; rest served by L2

// Monotone float -> uint mapping (order-preserving), and exact inverse.
__device__ __forceinline__ unsigned fkey(float f) {
    unsigned b = __float_as_uint(f);
    return ((int)b < 0) ? ~b : (b | 0x80000000u);
}
__device__ __forceinline__ float unfkey(unsigned k) {
    unsigned b = ((int)k < 0) ? (k & 0x7FFFFFFFu) : ~k;
    return __uint_as_float(b);
}

// Column ownership (0-based): lane owns col(k) = 64*(k>>1) + 2*lane + (k&1),
// k = 0..7 (4 adjacent pairs -> float2 loads, conflict-free LDS.64).
// Inverse: lane = (c0>>1)&31, k = ((c0>>6)<<1)|(c0&1).
__device__ __forceinline__ int colof(int lane, int k) {
    return 64 * (k >> 1) + 2 * lane + (k & 1);
}

// Jonker-Volgenant LAP (algorithm validated R6-R8):
//   phase 1: column reduction + SMEM row cache fill
//   phase 2: serial greedy assignment
//   phase 2b: bounded 3-pass augmenting row reduction
//   phase 3: single-warp absolute-distance Dijkstra augmentation
// R9: packed redux.max winner broadcast (replaces ballot/ffs/2xshfl tail);
// used columns poisoned via v[k] = -INF (kills usedmask test in the update
// loop; vsave[] restores v at end-of-row); ARR 3 passes.
__global__ __launch_bounds__(256, 1)
void lap_jv9(const float* __restrict__ C, float* __restrict__ out) {
    extern __shared__ float smem_dyn[];
    float* Ccache = smem_dyn;                      // [CROWS][256]
    float* u0     = Ccache + CROWS * 256;          // [N+1]
    float* vinit  = u0 + (N + 1);                  // [N+1]
    int*   p      = (int*)(vinit + (N + 1));       // [N+1] col -> row (0=free)
    int*   way    = p + (N + 1);                   // [N+1]
    int*   rmin   = way + (N + 1);                 // [N+1]
    int*   xrow   = rmin + (N + 1);                // [N+1]
    int*   lista  = xrow + (N + 1);                // [N]
    int*   listb  = lista + N;                     // [N]
    int*   sh_nfree = listb + N;                   // [1]

    const int tid = threadIdx.x;

    // ---- phase 1: column reduction + fill SMEM row cache (coalesced)
    {
        float best = C[tid];
        int   bi   = 0;
        Ccache[tid] = best;                        // row 0
        #pragma unroll 8
        for (int i = 1; i < N; ++i) {
            const float c = C[i * N + tid];
            if (i < CROWS) Ccache[i * 256 + tid] = c;
            if (c < best) { best = c; bi = i; }
        }
        vinit[tid + 1] = best;
        rmin[tid + 1]  = bi + 1;
        u0[tid + 1]    = 0.0f;
        p[tid + 1]     = 0;
        xrow[tid + 1]  = 0;
        if (tid == 0) { u0[0] = 0.0f; vinit[0] = 0.0f; p[0] = 0; xrow[0] = 0; }
    }
    __syncthreads();

    // ---- phase 2: greedy assignment (serial, short)
    if (tid == 0) {
        for (int j = 1; j <= N; ++j) {
            const int r = rmin[j];
            if (xrow[r] == 0) { xrow[r] = j; p[j] = r; }
        }
        int nf = 0;
        for (int r = 1; r <= N; ++r) if (xrow[r] == 0) lista[nf++] = r;
        *sh_nfree = nf;
    }
    __syncthreads();

    if (tid < 32) {
        const int lane = tid;
        float v[8], dist[8], mark[8], vsave[8];
        #pragma unroll
        for (int k = 0; k < 8; ++k) v[k] = vinit[colof(lane, k) + 1];

        // ---- phase 2b: bounded ARR, 3 passes, kicked rows -> next list
        int nf_cur = *sh_nfree;
        int* cur  = lista;
        int* nxt  = listb;
        #pragma unroll 1
        for (int pass = 0; pass < 3; ++pass) {
            int nf_nxt = 0;
            for (int kq = 0; kq < nf_cur; ++kq) {
                const int i = cur[kq];

                // warp scan of row i: min1 (argmin col) + min2 of C - v
                float d[8];
                if (i <= CROWS) {
                    const float* rs = Ccache + (i - 1) * 256 + 2 * lane;
                    #pragma unroll
                    for (int s = 0; s < 4; ++s) {
                        const float2 t = *(const float2*)(rs + 64 * s);
                        d[2 * s]     = t.x - v[2 * s];
                        d[2 * s + 1] = t.y - v[2 * s + 1];
                    }
                } else {
                    const float* rowp = C + (i - 1) * N + 2 * lane;
                    #pragma unroll
                    for (int s = 0; s < 4; ++s) {
                        const float2 t = __ldg((const float2*)(rowp + 64 * s));
                        d[2 * s]     = t.x - v[2 * s];
                        d[2 * s + 1] = t.y - v[2 * s + 1];
                    }
                }
                float m1 = d[0], m2 = BIG;
                int bk = 0;
                #pragma unroll
                for (int s = 1; s < 8; ++s) {
                    if (d[s] < m1)      { m2 = m1; m1 = d[s]; bk = s; }
                    else if (d[s] < m2) { m2 = d[s]; }
                }
                int jmin = colof(lane, bk) + 1;
                #pragma unroll
                for (int off = 16; off; off >>= 1) {
                    const float om1 = __shfl_xor_sync(0xFFFFFFFFu, m1, off);
                    const int   oj  = __shfl_xor_sync(0xFFFFFFFFu, jmin, off);
                    const float om2 = __shfl_xor_sync(0xFFFFFFFFu, m2, off);
                    m2 = fminf(fminf(m2, om2), fmaxf(m1, om1));
                    if (om1 < m1) { m1 = om1; jmin = oj; }
                }

                const int   i0    = p[jmin];          // uniform
                const float delta = m2 - m1;
                if (delta > 0.0f || i0 == 0) {
                    const int c0 = jmin - 1;
                    if (((c0 >> 1) & 31) == lane)
                        v[((c0 >> 6) << 1) | (c0 & 1)] -= delta;
                    if (lane == 0) { u0[i] = m2; p[jmin] = i; }
                    if (i0 != 0) {                    // kicked -> next pass
                        if (lane == 0) nxt[nf_nxt] = i0;
                        ++nf_nxt;
                    }
                } else {                              // tie on occupied col
                    if (lane == 0) nxt[nf_nxt] = i;
                    ++nf_nxt;
                }
                __syncwarp();
            }
            nf_cur = nf_nxt;
            int* t = cur; cur = nxt; nxt = t;
        }

        // ---- phase 3: Dijkstra augmentation per remaining free row
        const int nf = nf_cur;
        for (int fr = 0; fr < nf; ++fr) {
            const int i = cur[fr];
            #pragma unroll
            for (int k = 0; k < 8; ++k) dist[k] = BIG;
            unsigned usedmask = 0;
            float Dsum = 0.0f;
            int j0 = 0, i0 = i, jfree;
            if (lane == 0) p[0] = i;

            for (;;) {
                // row loads first (v2); bookkeeping in their shadow
                float cc[8];
                if (i0 <= CROWS) {
                    const float* rs = Ccache + (i0 - 1) * 256 + 2 * lane;
                    #pragma unroll
                    for (int s = 0; s < 4; ++s) {
                        const float2 t = *(const float2*)(rs + 64 * s);
                        cc[2 * s] = t.x; cc[2 * s + 1] = t.y;
                    }
                } else {
                    const float* rowp = C + (i0 - 1) * N + 2 * lane;
                    #pragma unroll
                    for (int s = 0; s < 4; ++s) {
                        const float2 t = __ldg((const float2*)(rowp + 64 * s));
                        cc[2 * s] = t.x; cc[2 * s + 1] = t.y;
                    }
                }
                const float s0 = Dsum - u0[i0];

                // mark popped column j0: freeze value, poison v, kill dist
                if (j0) {
                    const int c0 = j0 - 1;
                    if (((c0 >> 1) & 31) == lane) {
                        const int k = ((c0 >> 6) << 1) | (c0 & 1);
                        usedmask |= 1u << k;
                        mark[k]  = Dsum;
                        vsave[k] = v[k];
                        v[k]     = -FINF;   // cur_d becomes +INF forever
                        dist[k]  = FINF;
                    }
                }

                // update loop: no used test needed (poisoned cols give INF)
                #pragma unroll
                for (int k = 0; k < 8; ++k) {
                    const float cur_d = (cc[k] - v[k]) + s0;
                    if (cur_d < dist[k]) {
                        dist[k] = cur_d;
                        way[colof(lane, k) + 1] = j0;
                    }
                }

                // min tree directly on dist (used entries are +INF)
                const float t0 = fminf(dist[0], dist[1]);
                const float t1 = fminf(dist[2], dist[3]);
                const float t2 = fminf(dist[4], dist[5]);
                const float t3 = fminf(dist[6], dist[7]);
                const float bv = fminf(fminf(t0, t1), fminf(t2, t3));

                const unsigned key  = fkey(bv);
                const unsigned kmin = __reduce_min_sync(0xFFFFFFFFu, key);

                int bk = 7;
                #pragma unroll
                for (int k = 6; k >= 0; --k) bk = (dist[k] == bv) ? k : bk;
                const int jc = colof(lane, bk) + 1;
                const int ic = p[jc];                 // overlaps redux.min

                // packed winner broadcast: one coherent (jc, ic) even on ties
                const unsigned packed =
                    (key == kmin) ? (unsigned)(jc | (ic << 9)) : 0u;
                const unsigned win = __reduce_max_sync(0xFFFFFFFFu, packed);
                Dsum = unfkey(kmin);
                j0 = (int)(win & 511u);
                i0 = (int)(win >> 9);
                if (i0 == 0) { jfree = j0; break; }
            }

            // end-of-row dual updates; restore poisoned v from vsave
            const float Dfinal = Dsum;
            #pragma unroll
            for (int k = 0; k < 8; ++k) {
                if ((usedmask >> k) & 1u) {
                    const float amt = Dfinal - mark[k];
                    v[k] = vsave[k] - amt;
                    u0[p[colof(lane, k) + 1]] += amt; // distinct rows: safe
                }
            }
            if (lane == 0) u0[i] += Dfinal;
            __syncwarp();

            if (lane == 0) {                          // augment path
                int jj = jfree;
                while (jj != 0) { const int j1 = way[jj]; p[jj] = p[j1]; jj = j1; }
            }
            __syncwarp();
        }
    }
    __syncthreads();

    // ---- output: 0/1 labelling
    {
        const float4 z = make_float4(0.f, 0.f, 0.f, 0.f);
        for (int idx = tid; idx < N * N / 4; idx += 256) ((float4*)out)[idx] = z;
    }
    __syncthreads();
    {
        const int col = tid;                          // 0-based column
        const int r   = p[col + 1] - 1;               // 0-based matched row
        out[r * N + col] = 1.0f;
    }
}

// Dynamic SMEM size: C cache + solver state
#define SMEM_BYTES (CROWS * 256 * 4 + 2 * (N + 1) * 4 + 4 * (N + 1) * 4 \
                    + 2 * N * 4 + 4)

extern "C" void kernel_launch(void* const* d_in, const int* in_sizes, int n_in,
                              void* d_out, int out_size) {
    (void)in_sizes; (void)n_in; (void)out_size;
    cudaFuncSetAttribute(lap_jv9, cudaFuncAttributeMaxDynamicSharedMemorySize,
                         SMEM_BYTES);
    lap_jv9<<<1, 256, SMEM_BYTES>>>((const float*)d_in[0], (float*)d_out);
}